// round 13
// baseline (speedup 1.0000x reference)
#include <cuda_runtime.h>
#include <cuda_fp16.h>
#include <cstdint>
#include <math.h>

#define NN   50000
#define EE   850000
#define FIN  128
#define NH1  4
#define C1   50
#define HID  200
#define FOUT 40
#define K2P  208

#define SCAN_B 256
#define SCAN_NB ((NN + SCAN_B - 1) / SCAN_B)   // 196

// gemm tiling: 4 warps x 16 rows = 64 rows per block (R7 config)
#define G_THREADS 128
#define G_ROWS    64
#define G_BLOCKS  ((NN + G_ROWS - 1) / G_ROWS)   // 782
#define XS_STRIDE  136
#define WT_STRIDE  136
#define XS2_STRIDE 216
#define WT2_STRIDE 216

#define AGG_THREADS 256
#define AGG_WARPS   (AGG_THREADS / 32)

// ---------------- scratch ----------------
__device__ __half g_H1h[NN * HID];
__device__ __half g_H2h[NN * K2P];
__device__ __half g_G2h[NN * FOUT];
__device__ __half g_W1t[HID * FIN];
__device__ __half g_W2t[FOUT * K2P];
__device__ float g_as1[NN * NH1];
__device__ float g_ad1[NN * NH1];
__device__ float g_as2[NN];
__device__ float g_ad2[NN];
__device__ int   g_deg[NN];
__device__ int   g_rowptr[NN + 1];
__device__ int   g_cursor[NN];
__device__ int   g_csrc[EE];
__device__ int   g_bsum[SCAN_NB];
__device__ int   g_boff[SCAN_NB];
__device__ int   g_flag32;

__device__ __forceinline__ int load_idx(const void* p, int e, int is64) {
    if (is64) return (int)((const long long*)p)[e];
    return ((const int*)p)[e];
}

// ---------------- prep: weights -> fp16 transposed (side stream) ----------
__global__ void k_prep(const float* __restrict__ W1, const float* __restrict__ W2) {
    int i = blockIdx.x * blockDim.x + threadIdx.x;
    if (i < FIN * HID) {
        int n = i / FIN, k = i % FIN;
        g_W1t[n * FIN + k] = __float2half_rn(W1[k * HID + n]);
    }
    if (i < FOUT * K2P) {
        int n = i / K2P, k = i % K2P;
        g_W2t[i] = (k < HID) ? __float2half_rn(W2[k * FOUT + n]) : __float2half_rn(0.f);
    }
}

// ---------------- graph build (R11 exact) ----------------
__global__ void k_reset(const void* src) {
    int i = blockIdx.x * blockDim.x + threadIdx.x;
    if (i == 0) g_flag32 = 0;
    if (i < NN) g_deg[i] = 0;
    if (i >= NN && i < NN + 4096) {
        int t = i - NN;
        if (((const int*)src)[2 * t + 1] != 0) atomicOr(&g_flag32, 1);
    }
}

__global__ void k_count(const void* dst) {
    int e = blockIdx.x * blockDim.x + threadIdx.x;
    if (e < EE) {
        int is64 = (g_flag32 == 0);
        int d = load_idx(dst, e, is64);
        atomicAdd(&g_deg[d], 1);
    }
}

__global__ void k_scanA() {
    __shared__ int sh[SCAN_B];
    int t = threadIdx.x;
    int i = blockIdx.x * SCAN_B + t;
    int v = (i < NN) ? g_deg[i] : 0;
    sh[t] = v;
    __syncthreads();
    #pragma unroll
    for (int off = 1; off < SCAN_B; off <<= 1) {
        int add = (t >= off) ? sh[t - off] : 0;
        __syncthreads();
        sh[t] += add;
        __syncthreads();
    }
    if (i < NN) g_rowptr[i] = sh[t] - v;
    if (t == SCAN_B - 1) g_bsum[blockIdx.x] = sh[t];
}

__global__ void k_scanB() {
    __shared__ int sh[SCAN_B];
    int t = threadIdx.x;
    int v = (t < SCAN_NB) ? g_bsum[t] : 0;
    sh[t] = v;
    __syncthreads();
    #pragma unroll
    for (int off = 1; off < SCAN_B; off <<= 1) {
        int add = (t >= off) ? sh[t - off] : 0;
        __syncthreads();
        sh[t] += add;
        __syncthreads();
    }
    if (t < SCAN_NB) g_boff[t] = sh[t] - v;
}

__global__ void k_scanC() {
    int i = blockIdx.x * SCAN_B + threadIdx.x;
    if (i < NN) {
        int r = g_rowptr[i] + g_boff[blockIdx.x];
        g_rowptr[i] = r;
        g_cursor[i] = r;
    }
    if (i == 0) g_rowptr[NN] = EE;
}

__global__ void k_fill(const void* src, const void* dst) {
    int e = blockIdx.x * blockDim.x + threadIdx.x;
    if (e < EE) {
        int is64 = (g_flag32 == 0);
        int s = load_idx(src, e, is64);
        int d = load_idx(dst, e, is64);
        int pos = atomicAdd(&g_cursor[d], 1);
        g_csrc[pos] = s;
    }
}

// ---------------- GEMM1 (tensor cores, 64 rows/block — R7) -----------------
__global__ void __launch_bounds__(G_THREADS) k_gemm1(
        const float* __restrict__ x,
        const float* __restrict__ aw_s, const float* __restrict__ aw_d) {
    extern __shared__ char smraw[];
    __half* xs = (__half*)smraw;                              // 64 x 136
    __half* wt = (__half*)(smraw + G_ROWS * XS_STRIDE * 2);   // 200 x 136
    float* As = (float*)(smraw + G_ROWS * XS_STRIDE * 2 + HID * WT_STRIDE * 2);
    float* Ad = As + HID;

    int tid = threadIdx.x;
    int rowbase = blockIdx.x * G_ROWS;

    for (int idx = tid; idx < G_ROWS * (FIN / 4); idx += G_THREADS) {
        int r = idx >> 5;
        int c4 = idx & 31;
        float4 v = (rowbase + r < NN) ? *(const float4*)(x + (size_t)(rowbase + r) * FIN + c4 * 4)
                                      : make_float4(0.f, 0.f, 0.f, 0.f);
        __half2 h01 = __float22half2_rn(make_float2(v.x, v.y));
        __half2 h23 = __float22half2_rn(make_float2(v.z, v.w));
        uint2 pk = make_uint2(*(unsigned int*)&h01, *(unsigned int*)&h23);
        *(uint2*)(xs + r * XS_STRIDE + c4 * 4) = pk;
    }
    for (int idx = tid; idx < HID * (FIN / 8); idx += G_THREADS) {
        int n = idx >> 4, c = idx & 15;
        *(uint4*)(wt + n * WT_STRIDE + c * 8) = *(const uint4*)(g_W1t + n * FIN + c * 8);
    }
    for (int i = tid; i < HID; i += G_THREADS) { As[i] = aw_s[i]; Ad[i] = aw_d[i]; }
    __syncthreads();

    int warp = tid >> 5, lane = tid & 31;
    int g = lane >> 2, t = lane & 3;
    int lrow0 = warp * 16 + g;

    float c[25][4];
    #pragma unroll
    for (int nt = 0; nt < 25; nt++) { c[nt][0] = c[nt][1] = c[nt][2] = c[nt][3] = 0.f; }

    #pragma unroll
    for (int ks = 0; ks < 8; ks++) {
        int k0 = ks * 16;
        unsigned int a0 = *(const unsigned int*)(xs + lrow0 * XS_STRIDE + k0 + 2 * t);
        unsigned int a1 = *(const unsigned int*)(xs + (lrow0 + 8) * XS_STRIDE + k0 + 2 * t);
        unsigned int a2 = *(const unsigned int*)(xs + lrow0 * XS_STRIDE + k0 + 2 * t + 8);
        unsigned int a3 = *(const unsigned int*)(xs + (lrow0 + 8) * XS_STRIDE + k0 + 2 * t + 8);
        #pragma unroll
        for (int nt = 0; nt < 25; nt++) {
            unsigned int b0 = *(const unsigned int*)(wt + (nt * 8 + g) * WT_STRIDE + k0 + 2 * t);
            unsigned int b1 = *(const unsigned int*)(wt + (nt * 8 + g) * WT_STRIDE + k0 + 2 * t + 8);
            asm volatile(
                "mma.sync.aligned.m16n8k16.row.col.f32.f16.f16.f32 "
                "{%0,%1,%2,%3},{%4,%5,%6,%7},{%8,%9},{%0,%1,%2,%3};"
                : "+f"(c[nt][0]), "+f"(c[nt][1]), "+f"(c[nt][2]), "+f"(c[nt][3])
                : "r"(a0), "r"(a1), "r"(a2), "r"(a3), "r"(b0), "r"(b1));
        }
    }

    int r0 = rowbase + lrow0;
    int r1 = r0 + 8;
    float psl0 = 0, psl1 = 0, psl2 = 0, psl3 = 0;
    float pdl0 = 0, pdl1 = 0, pdl2 = 0, pdl3 = 0;
    float psh0 = 0, psh1 = 0, psh2 = 0, psh3 = 0;
    float pdh0 = 0, pdh1 = 0, pdh2 = 0, pdh3 = 0;

    #pragma unroll
    for (int nt = 0; nt < 25; nt++) {
        int col = nt * 8 + 2 * t;
        int h = col / 50;
        float as0 = As[col], as1v = As[col + 1];
        float ad0 = Ad[col], ad1v = Ad[col + 1];
        float sl = c[nt][0] * as0 + c[nt][1] * as1v;
        float dl = c[nt][0] * ad0 + c[nt][1] * ad1v;
        float sh = c[nt][2] * as0 + c[nt][3] * as1v;
        float dh = c[nt][2] * ad0 + c[nt][3] * ad1v;
        if (h == 0)      { psl0 += sl; pdl0 += dl; psh0 += sh; pdh0 += dh; }
        else if (h == 1) { psl1 += sl; pdl1 += dl; psh1 += sh; pdh1 += dh; }
        else if (h == 2) { psl2 += sl; pdl2 += dl; psh2 += sh; pdh2 += dh; }
        else             { psl3 += sl; pdl3 += dl; psh3 += sh; pdh3 += dh; }
        if (r0 < NN) {
            __half2 p = __float22half2_rn(make_float2(c[nt][0], c[nt][1]));
            *(unsigned int*)(g_H1h + (size_t)r0 * HID + col) = *(unsigned int*)&p;
        }
        if (r1 < NN) {
            __half2 p = __float22half2_rn(make_float2(c[nt][2], c[nt][3]));
            *(unsigned int*)(g_H1h + (size_t)r1 * HID + col) = *(unsigned int*)&p;
        }
    }
    #pragma unroll
    for (int off = 1; off <= 2; off <<= 1) {
        psl0 += __shfl_xor_sync(~0u, psl0, off); psl1 += __shfl_xor_sync(~0u, psl1, off);
        psl2 += __shfl_xor_sync(~0u, psl2, off); psl3 += __shfl_xor_sync(~0u, psl3, off);
        pdl0 += __shfl_xor_sync(~0u, pdl0, off); pdl1 += __shfl_xor_sync(~0u, pdl1, off);
        pdl2 += __shfl_xor_sync(~0u, pdl2, off); pdl3 += __shfl_xor_sync(~0u, pdl3, off);
        psh0 += __shfl_xor_sync(~0u, psh0, off); psh1 += __shfl_xor_sync(~0u, psh1, off);
        psh2 += __shfl_xor_sync(~0u, psh2, off); psh3 += __shfl_xor_sync(~0u, psh3, off);
        pdh0 += __shfl_xor_sync(~0u, pdh0, off); pdh1 += __shfl_xor_sync(~0u, pdh1, off);
        pdh2 += __shfl_xor_sync(~0u, pdh2, off); pdh3 += __shfl_xor_sync(~0u, pdh3, off);
    }
    if (t == 0) {
        if (r0 < NN) {
            g_as1[r0 * 4 + 0] = psl0; g_as1[r0 * 4 + 1] = psl1;
            g_as1[r0 * 4 + 2] = psl2; g_as1[r0 * 4 + 3] = psl3;
            g_ad1[r0 * 4 + 0] = pdl0; g_ad1[r0 * 4 + 1] = pdl1;
            g_ad1[r0 * 4 + 2] = pdl2; g_ad1[r0 * 4 + 3] = pdl3;
        }
        if (r1 < NN) {
            g_as1[r1 * 4 + 0] = psh0; g_as1[r1 * 4 + 1] = psh1;
            g_as1[r1 * 4 + 2] = psh2; g_as1[r1 * 4 + 3] = psh3;
            g_ad1[r1 * 4 + 0] = pdh0; g_ad1[r1 * 4 + 1] = pdh1;
            g_ad1[r1 * 4 + 2] = pdh2; g_ad1[r1 * 4 + 3] = pdh3;
        }
    }
}

// ---------------- agg layer 1: smem vector-broadcast of (u, p0..p3) --------
__global__ void __launch_bounds__(AGG_THREADS) k_agg1(const float* __restrict__ b1) {
    __shared__ float4 sp4[AGG_WARPS][32];
    __shared__ float  sp1[AGG_WARPS][32];

    int v = (blockIdx.x * blockDim.x + threadIdx.x) >> 5;
    int warp = threadIdx.x >> 5;
    int lane = threadIdx.x & 31;
    if (v >= NN) return;
    int beg = g_rowptr[v], end = g_rowptr[v + 1];
    float4 adv = *(const float4*)(g_ad1 + v * 4);

    int hh[4];
    #pragma unroll
    for (int j = 0; j < 4; j++) hh[j] = (j * 32 + lane) / 25;
    float acc[4][2] = {{0,0},{0,0},{0,0},{0,0}};
    float s0 = 0.f, s1 = 0.f, s2 = 0.f, s3 = 0.f;

    for (int base = beg; base < end; base += 32) {
        int cnt = min(32, end - base);
        __syncwarp();                      // WAR: prior chunk reads done
        if (lane < cnt) {
            int u = __ldg(g_csrc + base + lane);
            float4 a = *(const float4*)(g_as1 + u * 4);
            float e0 = a.x + adv.x; e0 = e0 > 0.f ? e0 : 0.2f * e0;
            float e1 = a.y + adv.y; e1 = e1 > 0.f ? e1 : 0.2f * e1;
            float e2 = a.z + adv.z; e2 = e2 > 0.f ? e2 : 0.2f * e2;
            float e3 = a.w + adv.w; e3 = e3 > 0.f ? e3 : 0.2f * e3;
            float p0 = __expf(e0), p1 = __expf(e1), p2 = __expf(e2), p3 = __expf(e3);
            s0 += p0; s1 += p1; s2 += p2; s3 += p3;
            sp4[warp][lane] = make_float4(__int_as_float(u), p0, p1, p2);
            sp1[warp][lane] = p3;
        }
        __syncwarp();
        for (int t = 0; t < cnt; t++) {
            float4 w = sp4[warp][t];       // LDS.128 broadcast
            int uu = __float_as_int(w.x);
            float q3 = sp1[warp][t];       // LDS.32 broadcast
            const __half2* hr = (const __half2*)(g_H1h + (size_t)uu * HID);
            #pragma unroll
            for (int j = 0; j < 4; j++) {
                if (j < 3 || lane < 4) {
                    float2 f = __half22float2(hr[j * 32 + lane]);
                    float q = hh[j] == 0 ? w.y : (hh[j] == 1 ? w.z : (hh[j] == 2 ? w.w : q3));
                    acc[j][0] = fmaf(q, f.x, acc[j][0]);
                    acc[j][1] = fmaf(q, f.y, acc[j][1]);
                }
            }
        }
    }
    #pragma unroll
    for (int off = 16; off; off >>= 1) {
        s0 += __shfl_xor_sync(~0u, s0, off); s1 += __shfl_xor_sync(~0u, s1, off);
        s2 += __shfl_xor_sync(~0u, s2, off); s3 += __shfl_xor_sync(~0u, s3, off);
    }
    float is0 = 1.f / s0, is1 = 1.f / s1, is2 = 1.f / s2, is3 = 1.f / s3;
    #pragma unroll
    for (int j = 0; j < 4; j++) {
        if (j < 3 || lane < 4) {
            int idx = j * 32 + lane;
            float iv = hh[j] == 0 ? is0 : (hh[j] == 1 ? is1 : (hh[j] == 2 ? is2 : is3));
            float v0 = acc[j][0] * iv + __ldg(b1 + 2 * idx);
            float v1 = acc[j][1] * iv + __ldg(b1 + 2 * idx + 1);
            v0 = v0 > 0.f ? v0 : expm1f(v0);
            v1 = v1 > 0.f ? v1 : expm1f(v1);
            __half2 p = __float22half2_rn(make_float2(v0, v1));
            *(unsigned int*)(g_H2h + (size_t)v * K2P + 2 * idx) = *(unsigned int*)&p;
        }
    }
}

// ---------------- GEMM2 (tensor cores, 64 rows/block — R7) -----------------
__global__ void __launch_bounds__(G_THREADS) k_gemm2(
        const float* __restrict__ aw_s, const float* __restrict__ aw_d) {
    extern __shared__ char smraw[];
    __half* xs = (__half*)smraw;                               // 64 x 216
    __half* wt = (__half*)(smraw + G_ROWS * XS2_STRIDE * 2);   // 40 x 216
    float* As = (float*)(smraw + G_ROWS * XS2_STRIDE * 2 + FOUT * WT2_STRIDE * 2);
    float* Ad = As + FOUT;

    int tid = threadIdx.x;
    int rowbase = blockIdx.x * G_ROWS;

    for (int idx = tid; idx < G_ROWS * 26; idx += G_THREADS) {
        int r = idx / 26, c = idx % 26;
        uint4 v;
        if (rowbase + r < NN) v = *(const uint4*)(g_H2h + (size_t)(rowbase + r) * K2P + c * 8);
        else v = make_uint4(0u, 0u, 0u, 0u);
        *(uint4*)(xs + r * XS2_STRIDE + c * 8) = v;
    }
    for (int idx = tid; idx < FOUT * 26; idx += G_THREADS) {
        int n = idx / 26, c = idx % 26;
        *(uint4*)(wt + n * WT2_STRIDE + c * 8) = *(const uint4*)(g_W2t + n * K2P + c * 8);
    }
    for (int i = tid; i < FOUT; i += G_THREADS) { As[i] = aw_s[i]; Ad[i] = aw_d[i]; }
    __syncthreads();

    int warp = tid >> 5, lane = tid & 31;
    int g = lane >> 2, t = lane & 3;
    int lrow0 = warp * 16 + g;

    float c[5][4];
    #pragma unroll
    for (int nt = 0; nt < 5; nt++) { c[nt][0] = c[nt][1] = c[nt][2] = c[nt][3] = 0.f; }

    #pragma unroll
    for (int ks = 0; ks < 13; ks++) {
        int k0 = ks * 16;
        unsigned int a0 = *(const unsigned int*)(xs + lrow0 * XS2_STRIDE + k0 + 2 * t);
        unsigned int a1 = *(const unsigned int*)(xs + (lrow0 + 8) * XS2_STRIDE + k0 + 2 * t);
        unsigned int a2 = *(const unsigned int*)(xs + lrow0 * XS2_STRIDE + k0 + 2 * t + 8);
        unsigned int a3 = *(const unsigned int*)(xs + (lrow0 + 8) * XS2_STRIDE + k0 + 2 * t + 8);
        #pragma unroll
        for (int nt = 0; nt < 5; nt++) {
            unsigned int b0 = *(const unsigned int*)(wt + (nt * 8 + g) * WT2_STRIDE + k0 + 2 * t);
            unsigned int b1 = *(const unsigned int*)(wt + (nt * 8 + g) * WT2_STRIDE + k0 + 2 * t + 8);
            asm volatile(
                "mma.sync.aligned.m16n8k16.row.col.f32.f16.f16.f32 "
                "{%0,%1,%2,%3},{%4,%5,%6,%7},{%8,%9},{%0,%1,%2,%3};"
                : "+f"(c[nt][0]), "+f"(c[nt][1]), "+f"(c[nt][2]), "+f"(c[nt][3])
                : "r"(a0), "r"(a1), "r"(a2), "r"(a3), "r"(b0), "r"(b1));
        }
    }

    int r0 = rowbase + lrow0;
    int r1 = r0 + 8;
    float psl = 0, pdl = 0, psh = 0, pdh = 0;
    #pragma unroll
    for (int nt = 0; nt < 5; nt++) {
        int col = nt * 8 + 2 * t;
        float as0 = As[col], as1v = As[col + 1];
        float ad0 = Ad[col], ad1v = Ad[col + 1];
        psl += c[nt][0] * as0 + c[nt][1] * as1v;
        pdl += c[nt][0] * ad0 + c[nt][1] * ad1v;
        psh += c[nt][2] * as0 + c[nt][3] * as1v;
        pdh += c[nt][2] * ad0 + c[nt][3] * ad1v;
        if (r0 < NN) {
            __half2 p = __float22half2_rn(make_float2(c[nt][0], c[nt][1]));
            *(unsigned int*)(g_G2h + (size_t)r0 * FOUT + col) = *(unsigned int*)&p;
        }
        if (r1 < NN) {
            __half2 p = __float22half2_rn(make_float2(c[nt][2], c[nt][3]));
            *(unsigned int*)(g_G2h + (size_t)r1 * FOUT + col) = *(unsigned int*)&p;
        }
    }
    #pragma unroll
    for (int off = 1; off <= 2; off <<= 1) {
        psl += __shfl_xor_sync(~0u, psl, off);
        pdl += __shfl_xor_sync(~0u, pdl, off);
        psh += __shfl_xor_sync(~0u, psh, off);
        pdh += __shfl_xor_sync(~0u, pdh, off);
    }
    if (t == 0) {
        if (r0 < NN) { g_as2[r0] = psl; g_ad2[r0] = pdl; }
        if (r1 < NN) { g_as2[r1] = psh; g_ad2[r1] = pdh; }
    }
}

// ---------------- agg layer 2 + log_softmax (smem broadcast) ----------------
__global__ void __launch_bounds__(AGG_THREADS) k_agg2(
        const float* __restrict__ b2, float* __restrict__ out) {
    __shared__ float2 sp2[AGG_WARPS][32];

    int v = (blockIdx.x * blockDim.x + threadIdx.x) >> 5;
    int warp = threadIdx.x >> 5;
    int lane = threadIdx.x & 31;
    if (v >= NN) return;
    int beg = g_rowptr[v], end = g_rowptr[v + 1];
    float adv = g_ad2[v];

    float s = 0.f;
    float cx = 0.f, cy = 0.f;
    for (int base = beg; base < end; base += 32) {
        int cnt = min(32, end - base);
        __syncwarp();
        if (lane < cnt) {
            int u = __ldg(g_csrc + base + lane);
            float e = __ldg(g_as2 + u) + adv; e = e > 0.f ? e : 0.2f * e;
            float p = __expf(e);
            s += p;
            sp2[warp][lane] = make_float2(__int_as_float(u), p);
        }
        __syncwarp();
        for (int t = 0; t < cnt; t++) {
            float2 w = sp2[warp][t];        // LDS.64 broadcast
            int uu = __float_as_int(w.x);
            float q = w.y;
            if (lane < 20) {
                float2 f = __half22float2(((const __half2*)(g_G2h + (size_t)uu * FOUT))[lane]);
                cx = fmaf(q, f.x, cx);
                cy = fmaf(q, f.y, cy);
            }
        }
    }
    #pragma unroll
    for (int off = 16; off; off >>= 1) s += __shfl_xor_sync(~0u, s, off);

    float inv = 1.f / s;
    float o0 = (lane < 20) ? cx * inv + __ldg(b2 + 2 * lane)     : -1e30f;
    float o1 = (lane < 20) ? cy * inv + __ldg(b2 + 2 * lane + 1) : -1e30f;

    float mx = fmaxf(o0, o1);
    #pragma unroll
    for (int off = 16; off; off >>= 1) mx = fmaxf(mx, __shfl_xor_sync(~0u, mx, off));
    float se = (lane < 20) ? (__expf(o0 - mx) + __expf(o1 - mx)) : 0.f;
    #pragma unroll
    for (int off = 16; off; off >>= 1) se += __shfl_xor_sync(~0u, se, off);
    float ls = logf(se);

    if (lane < 20) {
        out[v * FOUT + 2 * lane]     = o0 - mx - ls;
        out[v * FOUT + 2 * lane + 1] = o1 - mx - ls;
    }
}

// ---------------- launch: fork-join streams (R11 exact) ----------------
extern "C" void kernel_launch(void* const* d_in, const int* in_sizes, int n_in,
                              void* d_out, int out_size) {
    const float* x    = (const float*)d_in[0];
    const void*  es   = d_in[1];
    const void*  ed   = d_in[2];
    const float* W1   = (const float*)d_in[3];
    const float* as1w = (const float*)d_in[4];
    const float* ad1w = (const float*)d_in[5];
    const float* b1   = (const float*)d_in[6];
    const float* W2   = (const float*)d_in[7];
    const float* as2w = (const float*)d_in[8];
    const float* ad2w = (const float*)d_in[9];
    const float* b2   = (const float*)d_in[10];
    float* out = (float*)d_out;

    static cudaStream_t s2 = 0;
    static cudaEvent_t evFork = 0, evJoin = 0;
    static int smemSet = 0;
    int smem1 = G_ROWS * XS_STRIDE * 2 + HID * WT_STRIDE * 2 + 2 * HID * 4;      // 73408
    int smem2 = G_ROWS * XS2_STRIDE * 2 + FOUT * WT2_STRIDE * 2 + 2 * FOUT * 4;  // 45248
    if (!s2) {
        cudaStreamCreateWithFlags(&s2, cudaStreamNonBlocking);
        cudaEventCreateWithFlags(&evFork, cudaEventDisableTiming);
        cudaEventCreateWithFlags(&evJoin, cudaEventDisableTiming);
    }
    if (!smemSet) {
        cudaFuncSetAttribute(k_gemm1, cudaFuncAttributeMaxDynamicSharedMemorySize, smem1);
        cudaFuncSetAttribute(k_gemm2, cudaFuncAttributeMaxDynamicSharedMemorySize, smem2);
        smemSet = 1;
    }

    // fork: side stream runs prep + gemm1 while default stream builds the CSR
    cudaEventRecord(evFork, 0);
    cudaStreamWaitEvent(s2, evFork, 0);

    k_prep<<<(FIN * HID + 255) / 256, 256, 0, s2>>>(W1, W2);
    k_gemm1<<<G_BLOCKS, G_THREADS, smem1, s2>>>(x, as1w, ad1w);

    k_reset<<<(NN + 4096 + 255) / 256, 256>>>(es);
    k_count<<<(EE + 255) / 256, 256>>>(ed);
    k_scanA<<<SCAN_NB, SCAN_B>>>();
    k_scanB<<<1, SCAN_B>>>();
    k_scanC<<<SCAN_NB, SCAN_B>>>();
    k_fill<<<(EE + 255) / 256, 256>>>(es, ed);

    // join
    cudaEventRecord(evJoin, s2);
    cudaStreamWaitEvent(0, evJoin, 0);

    k_agg1<<<(NN * 32 + AGG_THREADS - 1) / AGG_THREADS, AGG_THREADS>>>(b1);
    k_gemm2<<<G_BLOCKS, G_THREADS, smem2>>>(as2w, ad2w);
    k_agg2<<<(NN * 32 + AGG_THREADS - 1) / AGG_THREADS, AGG_THREADS>>>(b2, out);
}

// round 14
// speedup vs baseline: 1.0061x; 1.0061x over previous
#include <cuda_runtime.h>
#include <cuda_fp16.h>
#include <cstdint>
#include <math.h>

#define NN   50000
#define EE   850000
#define FIN  128
#define NH1  4
#define C1   50
#define HID  200
#define FOUT 40
#define K2P  208

#define SCAN_B 256
#define SCAN_NB ((NN + SCAN_B - 1) / SCAN_B)   // 196

// gemm tiling: 4 warps x 16 rows = 64 rows per block (R7 config)
#define G_THREADS 128
#define G_ROWS    64
#define G_BLOCKS  ((NN + G_ROWS - 1) / G_ROWS)   // 782
#define XS_STRIDE  136
#define WT_STRIDE  136
#define XS2_STRIDE 216
#define WT2_STRIDE 216

// ---------------- scratch ----------------
__device__ __half g_H1h[NN * HID];
__device__ __half g_H2h[NN * K2P];
__device__ __half g_G2h[NN * FOUT];
__device__ __half g_W1t[HID * FIN];
__device__ __half g_W2t[FOUT * K2P];
__device__ float g_as1[NN * NH1];
__device__ float g_ad1[NN * NH1];
__device__ float g_as2[NN];
__device__ float g_ad2[NN];
__device__ int   g_deg[NN];
__device__ int   g_rowptr[NN + 1];
__device__ int   g_cursor[NN];
__device__ int   g_csrc[EE];
__device__ int   g_bsum[SCAN_NB];
__device__ int   g_boff[SCAN_NB];
__device__ int   g_flag32;

// ---------------- prep: weights -> fp16 transposed (side stream) ----------
__global__ void k_prep(const float* __restrict__ W1, const float* __restrict__ W2) {
    int i = blockIdx.x * blockDim.x + threadIdx.x;
    if (i < FIN * HID) {
        int n = i / FIN, k = i % FIN;
        g_W1t[n * FIN + k] = __float2half_rn(W1[k * HID + n]);
    }
    if (i < FOUT * K2P) {
        int n = i / K2P, k = i % K2P;
        g_W2t[i] = (k < HID) ? __float2half_rn(W2[k * FOUT + n]) : __float2half_rn(0.f);
    }
}

// ---------------- graph build ----------------
// reset degrees + detect index dtype (int64 => high words all zero).
__global__ void k_reset(const void* src) {
    int i = blockIdx.x * blockDim.x + threadIdx.x;
    if (i == 0) g_flag32 = 0;
    if (i < NN) g_deg[i] = 0;
    if (i >= NN && i < NN + 4096) {
        int t = i - NN;
        if (((const int*)src)[2 * t + 1] != 0) atomicOr(&g_flag32, 1);
    }
}

// 2 edges per thread (vectorized index loads)
__global__ void k_count(const void* dst) {
    int idx = blockIdx.x * blockDim.x + threadIdx.x;
    int e = idx * 2;
    if (e < EE) {
        int d0, d1;
        if (g_flag32 == 0) {
            ulonglong2 p = ((const ulonglong2*)dst)[idx];
            d0 = (int)p.x; d1 = (int)p.y;
        } else {
            int2 p = ((const int2*)dst)[idx];
            d0 = p.x; d1 = p.y;
        }
        atomicAdd(&g_deg[d0], 1);
        atomicAdd(&g_deg[d1], 1);
    }
}

__global__ void k_scanA() {
    __shared__ int sh[SCAN_B];
    int t = threadIdx.x;
    int i = blockIdx.x * SCAN_B + t;
    int v = (i < NN) ? g_deg[i] : 0;
    sh[t] = v;
    __syncthreads();
    #pragma unroll
    for (int off = 1; off < SCAN_B; off <<= 1) {
        int add = (t >= off) ? sh[t - off] : 0;
        __syncthreads();
        sh[t] += add;
        __syncthreads();
    }
    if (i < NN) g_rowptr[i] = sh[t] - v;
    if (t == SCAN_B - 1) g_bsum[blockIdx.x] = sh[t];
}

__global__ void k_scanB() {
    __shared__ int sh[SCAN_B];
    int t = threadIdx.x;
    int v = (t < SCAN_NB) ? g_bsum[t] : 0;
    sh[t] = v;
    __syncthreads();
    #pragma unroll
    for (int off = 1; off < SCAN_B; off <<= 1) {
        int add = (t >= off) ? sh[t - off] : 0;
        __syncthreads();
        sh[t] += add;
        __syncthreads();
    }
    if (t < SCAN_NB) g_boff[t] = sh[t] - v;
}

__global__ void k_scanC() {
    int i = blockIdx.x * SCAN_B + threadIdx.x;
    if (i < NN) {
        int r = g_rowptr[i] + g_boff[blockIdx.x];
        g_rowptr[i] = r;
        g_cursor[i] = r;
    }
    if (i == 0) g_rowptr[NN] = EE;
}

// 2 edges per thread (vectorized index loads)
__global__ void k_fill(const void* src, const void* dst) {
    int idx = blockIdx.x * blockDim.x + threadIdx.x;
    int e = idx * 2;
    if (e < EE) {
        int s0, s1, d0, d1;
        if (g_flag32 == 0) {
            ulonglong2 ps = ((const ulonglong2*)src)[idx];
            ulonglong2 pd = ((const ulonglong2*)dst)[idx];
            s0 = (int)ps.x; s1 = (int)ps.y;
            d0 = (int)pd.x; d1 = (int)pd.y;
        } else {
            int2 ps = ((const int2*)src)[idx];
            int2 pd = ((const int2*)dst)[idx];
            s0 = ps.x; s1 = ps.y;
            d0 = pd.x; d1 = pd.y;
        }
        int p0 = atomicAdd(&g_cursor[d0], 1);
        g_csrc[p0] = s0;
        int p1 = atomicAdd(&g_cursor[d1], 1);
        g_csrc[p1] = s1;
    }
}

// ---------------- GEMM1 (tensor cores, 64 rows/block — R7) -----------------
__global__ void __launch_bounds__(G_THREADS) k_gemm1(
        const float* __restrict__ x,
        const float* __restrict__ aw_s, const float* __restrict__ aw_d) {
    extern __shared__ char smraw[];
    __half* xs = (__half*)smraw;                              // 64 x 136
    __half* wt = (__half*)(smraw + G_ROWS * XS_STRIDE * 2);   // 200 x 136
    float* As = (float*)(smraw + G_ROWS * XS_STRIDE * 2 + HID * WT_STRIDE * 2);
    float* Ad = As + HID;

    int tid = threadIdx.x;
    int rowbase = blockIdx.x * G_ROWS;

    for (int idx = tid; idx < G_ROWS * (FIN / 4); idx += G_THREADS) {
        int r = idx >> 5;
        int c4 = idx & 31;
        float4 v = (rowbase + r < NN) ? *(const float4*)(x + (size_t)(rowbase + r) * FIN + c4 * 4)
                                      : make_float4(0.f, 0.f, 0.f, 0.f);
        __half2 h01 = __float22half2_rn(make_float2(v.x, v.y));
        __half2 h23 = __float22half2_rn(make_float2(v.z, v.w));
        uint2 pk = make_uint2(*(unsigned int*)&h01, *(unsigned int*)&h23);
        *(uint2*)(xs + r * XS_STRIDE + c4 * 4) = pk;
    }
    for (int idx = tid; idx < HID * (FIN / 8); idx += G_THREADS) {
        int n = idx >> 4, c = idx & 15;
        *(uint4*)(wt + n * WT_STRIDE + c * 8) = *(const uint4*)(g_W1t + n * FIN + c * 8);
    }
    for (int i = tid; i < HID; i += G_THREADS) { As[i] = aw_s[i]; Ad[i] = aw_d[i]; }
    __syncthreads();

    int warp = tid >> 5, lane = tid & 31;
    int g = lane >> 2, t = lane & 3;
    int lrow0 = warp * 16 + g;

    float c[25][4];
    #pragma unroll
    for (int nt = 0; nt < 25; nt++) { c[nt][0] = c[nt][1] = c[nt][2] = c[nt][3] = 0.f; }

    #pragma unroll
    for (int ks = 0; ks < 8; ks++) {
        int k0 = ks * 16;
        unsigned int a0 = *(const unsigned int*)(xs + lrow0 * XS_STRIDE + k0 + 2 * t);
        unsigned int a1 = *(const unsigned int*)(xs + (lrow0 + 8) * XS_STRIDE + k0 + 2 * t);
        unsigned int a2 = *(const unsigned int*)(xs + lrow0 * XS_STRIDE + k0 + 2 * t + 8);
        unsigned int a3 = *(const unsigned int*)(xs + (lrow0 + 8) * XS_STRIDE + k0 + 2 * t + 8);
        #pragma unroll
        for (int nt = 0; nt < 25; nt++) {
            unsigned int b0 = *(const unsigned int*)(wt + (nt * 8 + g) * WT_STRIDE + k0 + 2 * t);
            unsigned int b1 = *(const unsigned int*)(wt + (nt * 8 + g) * WT_STRIDE + k0 + 2 * t + 8);
            asm volatile(
                "mma.sync.aligned.m16n8k16.row.col.f32.f16.f16.f32 "
                "{%0,%1,%2,%3},{%4,%5,%6,%7},{%8,%9},{%0,%1,%2,%3};"
                : "+f"(c[nt][0]), "+f"(c[nt][1]), "+f"(c[nt][2]), "+f"(c[nt][3])
                : "r"(a0), "r"(a1), "r"(a2), "r"(a3), "r"(b0), "r"(b1));
        }
    }

    int r0 = rowbase + lrow0;
    int r1 = r0 + 8;
    float psl0 = 0, psl1 = 0, psl2 = 0, psl3 = 0;
    float pdl0 = 0, pdl1 = 0, pdl2 = 0, pdl3 = 0;
    float psh0 = 0, psh1 = 0, psh2 = 0, psh3 = 0;
    float pdh0 = 0, pdh1 = 0, pdh2 = 0, pdh3 = 0;

    #pragma unroll
    for (int nt = 0; nt < 25; nt++) {
        int col = nt * 8 + 2 * t;
        int h = col / 50;
        float as0 = As[col], as1v = As[col + 1];
        float ad0 = Ad[col], ad1v = Ad[col + 1];
        float sl = c[nt][0] * as0 + c[nt][1] * as1v;
        float dl = c[nt][0] * ad0 + c[nt][1] * ad1v;
        float sh = c[nt][2] * as0 + c[nt][3] * as1v;
        float dh = c[nt][2] * ad0 + c[nt][3] * ad1v;
        if (h == 0)      { psl0 += sl; pdl0 += dl; psh0 += sh; pdh0 += dh; }
        else if (h == 1) { psl1 += sl; pdl1 += dl; psh1 += sh; pdh1 += dh; }
        else if (h == 2) { psl2 += sl; pdl2 += dl; psh2 += sh; pdh2 += dh; }
        else             { psl3 += sl; pdl3 += dl; psh3 += sh; pdh3 += dh; }
        if (r0 < NN) {
            __half2 p = __float22half2_rn(make_float2(c[nt][0], c[nt][1]));
            *(unsigned int*)(g_H1h + (size_t)r0 * HID + col) = *(unsigned int*)&p;
        }
        if (r1 < NN) {
            __half2 p = __float22half2_rn(make_float2(c[nt][2], c[nt][3]));
            *(unsigned int*)(g_H1h + (size_t)r1 * HID + col) = *(unsigned int*)&p;
        }
    }
    #pragma unroll
    for (int off = 1; off <= 2; off <<= 1) {
        psl0 += __shfl_xor_sync(~0u, psl0, off); psl1 += __shfl_xor_sync(~0u, psl1, off);
        psl2 += __shfl_xor_sync(~0u, psl2, off); psl3 += __shfl_xor_sync(~0u, psl3, off);
        pdl0 += __shfl_xor_sync(~0u, pdl0, off); pdl1 += __shfl_xor_sync(~0u, pdl1, off);
        pdl2 += __shfl_xor_sync(~0u, pdl2, off); pdl3 += __shfl_xor_sync(~0u, pdl3, off);
        psh0 += __shfl_xor_sync(~0u, psh0, off); psh1 += __shfl_xor_sync(~0u, psh1, off);
        psh2 += __shfl_xor_sync(~0u, psh2, off); psh3 += __shfl_xor_sync(~0u, psh3, off);
        pdh0 += __shfl_xor_sync(~0u, pdh0, off); pdh1 += __shfl_xor_sync(~0u, pdh1, off);
        pdh2 += __shfl_xor_sync(~0u, pdh2, off); pdh3 += __shfl_xor_sync(~0u, pdh3, off);
    }
    if (t == 0) {
        if (r0 < NN) {
            g_as1[r0 * 4 + 0] = psl0; g_as1[r0 * 4 + 1] = psl1;
            g_as1[r0 * 4 + 2] = psl2; g_as1[r0 * 4 + 3] = psl3;
            g_ad1[r0 * 4 + 0] = pdl0; g_ad1[r0 * 4 + 1] = pdl1;
            g_ad1[r0 * 4 + 2] = pdl2; g_ad1[r0 * 4 + 3] = pdl3;
        }
        if (r1 < NN) {
            g_as1[r1 * 4 + 0] = psh0; g_as1[r1 * 4 + 1] = psh1;
            g_as1[r1 * 4 + 2] = psh2; g_as1[r1 * 4 + 3] = psh3;
            g_ad1[r1 * 4 + 0] = pdh0; g_ad1[r1 * 4 + 1] = pdh1;
            g_ad1[r1 * 4 + 2] = pdh2; g_ad1[r1 * 4 + 3] = pdh3;
        }
    }
}

// ---------------- agg layer 1 (R11 shfl variant — measured best) -----------
__global__ void k_agg1(const float* __restrict__ b1) {
    int v = (blockIdx.x * blockDim.x + threadIdx.x) >> 5;
    int lane = threadIdx.x & 31;
    if (v >= NN) return;
    int beg = g_rowptr[v], end = g_rowptr[v + 1];
    float4 adv = *(const float4*)(g_ad1 + v * 4);

    int hh[4];
    #pragma unroll
    for (int j = 0; j < 4; j++) hh[j] = (j * 32 + lane) / 25;
    float acc[4][2] = {{0,0},{0,0},{0,0},{0,0}};
    float s0 = 0.f, s1 = 0.f, s2 = 0.f, s3 = 0.f;

    for (int base = beg; base < end; base += 32) {
        int cnt = min(32, end - base);
        int u = 0; float p0 = 0.f, p1 = 0.f, p2 = 0.f, p3 = 0.f;
        if (lane < cnt) {
            u = __ldg(g_csrc + base + lane);
            float4 a = *(const float4*)(g_as1 + u * 4);
            float e0 = a.x + adv.x; e0 = e0 > 0.f ? e0 : 0.2f * e0;
            float e1 = a.y + adv.y; e1 = e1 > 0.f ? e1 : 0.2f * e1;
            float e2 = a.z + adv.z; e2 = e2 > 0.f ? e2 : 0.2f * e2;
            float e3 = a.w + adv.w; e3 = e3 > 0.f ? e3 : 0.2f * e3;
            p0 = __expf(e0); p1 = __expf(e1); p2 = __expf(e2); p3 = __expf(e3);
        }
        s0 += p0; s1 += p1; s2 += p2; s3 += p3;
        for (int t = 0; t < cnt; t++) {
            int uu = __shfl_sync(0xffffffffu, u, t);
            float q0 = __shfl_sync(0xffffffffu, p0, t);
            float q1 = __shfl_sync(0xffffffffu, p1, t);
            float q2 = __shfl_sync(0xffffffffu, p2, t);
            float q3 = __shfl_sync(0xffffffffu, p3, t);
            const __half2* hr = (const __half2*)(g_H1h + (size_t)uu * HID);
            #pragma unroll
            for (int j = 0; j < 4; j++) {
                if (j < 3 || lane < 4) {
                    float2 f = __half22float2(hr[j * 32 + lane]);
                    float q = hh[j] == 0 ? q0 : (hh[j] == 1 ? q1 : (hh[j] == 2 ? q2 : q3));
                    acc[j][0] = fmaf(q, f.x, acc[j][0]);
                    acc[j][1] = fmaf(q, f.y, acc[j][1]);
                }
            }
        }
    }
    #pragma unroll
    for (int off = 16; off; off >>= 1) {
        s0 += __shfl_xor_sync(~0u, s0, off); s1 += __shfl_xor_sync(~0u, s1, off);
        s2 += __shfl_xor_sync(~0u, s2, off); s3 += __shfl_xor_sync(~0u, s3, off);
    }
    float is0 = 1.f / s0, is1 = 1.f / s1, is2 = 1.f / s2, is3 = 1.f / s3;
    #pragma unroll
    for (int j = 0; j < 4; j++) {
        if (j < 3 || lane < 4) {
            int idx = j * 32 + lane;
            float iv = hh[j] == 0 ? is0 : (hh[j] == 1 ? is1 : (hh[j] == 2 ? is2 : is3));
            float v0 = acc[j][0] * iv + __ldg(b1 + 2 * idx);
            float v1 = acc[j][1] * iv + __ldg(b1 + 2 * idx + 1);
            v0 = v0 > 0.f ? v0 : expm1f(v0);
            v1 = v1 > 0.f ? v1 : expm1f(v1);
            __half2 p = __float22half2_rn(make_float2(v0, v1));
            *(unsigned int*)(g_H2h + (size_t)v * K2P + 2 * idx) = *(unsigned int*)&p;
        }
    }
}

// ---------------- GEMM2 (tensor cores, 64 rows/block — R7) -----------------
__global__ void __launch_bounds__(G_THREADS) k_gemm2(
        const float* __restrict__ aw_s, const float* __restrict__ aw_d) {
    extern __shared__ char smraw[];
    __half* xs = (__half*)smraw;                               // 64 x 216
    __half* wt = (__half*)(smraw + G_ROWS * XS2_STRIDE * 2);   // 40 x 216
    float* As = (float*)(smraw + G_ROWS * XS2_STRIDE * 2 + FOUT * WT2_STRIDE * 2);
    float* Ad = As + FOUT;

    int tid = threadIdx.x;
    int rowbase = blockIdx.x * G_ROWS;

    for (int idx = tid; idx < G_ROWS * 26; idx += G_THREADS) {
        int r = idx / 26, c = idx % 26;
        uint4 v;
        if (rowbase + r < NN) v = *(const uint4*)(g_H2h + (size_t)(rowbase + r) * K2P + c * 8);
        else v = make_uint4(0u, 0u, 0u, 0u);
        *(uint4*)(xs + r * XS2_STRIDE + c * 8) = v;
    }
    for (int idx = tid; idx < FOUT * 26; idx += G_THREADS) {
        int n = idx / 26, c = idx % 26;
        *(uint4*)(wt + n * WT2_STRIDE + c * 8) = *(const uint4*)(g_W2t + n * K2P + c * 8);
    }
    for (int i = tid; i < FOUT; i += G_THREADS) { As[i] = aw_s[i]; Ad[i] = aw_d[i]; }
    __syncthreads();

    int warp = tid >> 5, lane = tid & 31;
    int g = lane >> 2, t = lane & 3;
    int lrow0 = warp * 16 + g;

    float c[5][4];
    #pragma unroll
    for (int nt = 0; nt < 5; nt++) { c[nt][0] = c[nt][1] = c[nt][2] = c[nt][3] = 0.f; }

    #pragma unroll
    for (int ks = 0; ks < 13; ks++) {
        int k0 = ks * 16;
        unsigned int a0 = *(const unsigned int*)(xs + lrow0 * XS2_STRIDE + k0 + 2 * t);
        unsigned int a1 = *(const unsigned int*)(xs + (lrow0 + 8) * XS2_STRIDE + k0 + 2 * t);
        unsigned int a2 = *(const unsigned int*)(xs + lrow0 * XS2_STRIDE + k0 + 2 * t + 8);
        unsigned int a3 = *(const unsigned int*)(xs + (lrow0 + 8) * XS2_STRIDE + k0 + 2 * t + 8);
        #pragma unroll
        for (int nt = 0; nt < 5; nt++) {
            unsigned int b0 = *(const unsigned int*)(wt + (nt * 8 + g) * WT2_STRIDE + k0 + 2 * t);
            unsigned int b1 = *(const unsigned int*)(wt + (nt * 8 + g) * WT2_STRIDE + k0 + 2 * t + 8);
            asm volatile(
                "mma.sync.aligned.m16n8k16.row.col.f32.f16.f16.f32 "
                "{%0,%1,%2,%3},{%4,%5,%6,%7},{%8,%9},{%0,%1,%2,%3};"
                : "+f"(c[nt][0]), "+f"(c[nt][1]), "+f"(c[nt][2]), "+f"(c[nt][3])
                : "r"(a0), "r"(a1), "r"(a2), "r"(a3), "r"(b0), "r"(b1));
        }
    }

    int r0 = rowbase + lrow0;
    int r1 = r0 + 8;
    float psl = 0, pdl = 0, psh = 0, pdh = 0;
    #pragma unroll
    for (int nt = 0; nt < 5; nt++) {
        int col = nt * 8 + 2 * t;
        float as0 = As[col], as1v = As[col + 1];
        float ad0 = Ad[col], ad1v = Ad[col + 1];
        psl += c[nt][0] * as0 + c[nt][1] * as1v;
        pdl += c[nt][0] * ad0 + c[nt][1] * ad1v;
        psh += c[nt][2] * as0 + c[nt][3] * as1v;
        pdh += c[nt][2] * ad0 + c[nt][3] * ad1v;
        if (r0 < NN) {
            __half2 p = __float22half2_rn(make_float2(c[nt][0], c[nt][1]));
            *(unsigned int*)(g_G2h + (size_t)r0 * FOUT + col) = *(unsigned int*)&p;
        }
        if (r1 < NN) {
            __half2 p = __float22half2_rn(make_float2(c[nt][2], c[nt][3]));
            *(unsigned int*)(g_G2h + (size_t)r1 * FOUT + col) = *(unsigned int*)&p;
        }
    }
    #pragma unroll
    for (int off = 1; off <= 2; off <<= 1) {
        psl += __shfl_xor_sync(~0u, psl, off);
        pdl += __shfl_xor_sync(~0u, pdl, off);
        psh += __shfl_xor_sync(~0u, psh, off);
        pdh += __shfl_xor_sync(~0u, pdh, off);
    }
    if (t == 0) {
        if (r0 < NN) { g_as2[r0] = psl; g_ad2[r0] = pdl; }
        if (r1 < NN) { g_as2[r1] = psh; g_ad2[r1] = pdh; }
    }
}

// ---------------- agg layer 2 + log_softmax (R11 shfl variant) -------------
__global__ void k_agg2(const float* __restrict__ b2, float* __restrict__ out) {
    int v = (blockIdx.x * blockDim.x + threadIdx.x) >> 5;
    int lane = threadIdx.x & 31;
    if (v >= NN) return;
    int beg = g_rowptr[v], end = g_rowptr[v + 1];
    float adv = g_ad2[v];

    float s = 0.f;
    float cx = 0.f, cy = 0.f;
    for (int base = beg; base < end; base += 32) {
        int cnt = min(32, end - base);
        int u = 0; float p = 0.f;
        if (lane < cnt) {
            u = __ldg(g_csrc + base + lane);
            float e = __ldg(g_as2 + u) + adv; e = e > 0.f ? e : 0.2f * e;
            p = __expf(e);
        }
        s += p;
        for (int t = 0; t < cnt; t++) {
            int uu = __shfl_sync(0xffffffffu, u, t);
            float q = __shfl_sync(0xffffffffu, p, t);
            if (lane < 20) {
                float2 f = __half22float2(((const __half2*)(g_G2h + (size_t)uu * FOUT))[lane]);
                cx = fmaf(q, f.x, cx);
                cy = fmaf(q, f.y, cy);
            }
        }
    }
    #pragma unroll
    for (int off = 16; off; off >>= 1) s += __shfl_xor_sync(~0u, s, off);

    float inv = 1.f / s;
    float o0 = (lane < 20) ? cx * inv + __ldg(b2 + 2 * lane)     : -1e30f;
    float o1 = (lane < 20) ? cy * inv + __ldg(b2 + 2 * lane + 1) : -1e30f;

    float mx = fmaxf(o0, o1);
    #pragma unroll
    for (int off = 16; off; off >>= 1) mx = fmaxf(mx, __shfl_xor_sync(~0u, mx, off));
    float se = (lane < 20) ? (__expf(o0 - mx) + __expf(o1 - mx)) : 0.f;
    #pragma unroll
    for (int off = 16; off; off >>= 1) se += __shfl_xor_sync(~0u, se, off);
    float ls = logf(se);

    if (lane < 20) {
        out[v * FOUT + 2 * lane]     = o0 - mx - ls;
        out[v * FOUT + 2 * lane + 1] = o1 - mx - ls;
    }
}

// ---------------- launch: fork-join streams (R11 exact) ----------------
extern "C" void kernel_launch(void* const* d_in, const int* in_sizes, int n_in,
                              void* d_out, int out_size) {
    const float* x    = (const float*)d_in[0];
    const void*  es   = d_in[1];
    const void*  ed   = d_in[2];
    const float* W1   = (const float*)d_in[3];
    const float* as1w = (const float*)d_in[4];
    const float* ad1w = (const float*)d_in[5];
    const float* b1   = (const float*)d_in[6];
    const float* W2   = (const float*)d_in[7];
    const float* as2w = (const float*)d_in[8];
    const float* ad2w = (const float*)d_in[9];
    const float* b2   = (const float*)d_in[10];
    float* out = (float*)d_out;

    static cudaStream_t s2 = 0;
    static cudaEvent_t evFork = 0, evJoin = 0;
    static int smemSet = 0;
    int smem1 = G_ROWS * XS_STRIDE * 2 + HID * WT_STRIDE * 2 + 2 * HID * 4;      // 73408
    int smem2 = G_ROWS * XS2_STRIDE * 2 + FOUT * WT2_STRIDE * 2 + 2 * FOUT * 4;  // 45248
    if (!s2) {
        cudaStreamCreateWithFlags(&s2, cudaStreamNonBlocking);
        cudaEventCreateWithFlags(&evFork, cudaEventDisableTiming);
        cudaEventCreateWithFlags(&evJoin, cudaEventDisableTiming);
    }
    if (!smemSet) {
        cudaFuncSetAttribute(k_gemm1, cudaFuncAttributeMaxDynamicSharedMemorySize, smem1);
        cudaFuncSetAttribute(k_gemm2, cudaFuncAttributeMaxDynamicSharedMemorySize, smem2);
        smemSet = 1;
    }

    // fork: side stream runs prep + gemm1 while default stream builds the CSR
    cudaEventRecord(evFork, 0);
    cudaStreamWaitEvent(s2, evFork, 0);

    k_prep<<<(FIN * HID + 255) / 256, 256, 0, s2>>>(W1, W2);
    k_gemm1<<<G_BLOCKS, G_THREADS, smem1, s2>>>(x, as1w, ad1w);

    k_reset<<<(NN + 4096 + 255) / 256, 256>>>(es);
    k_count<<<(EE / 2 + 255) / 256, 256>>>(ed);
    k_scanA<<<SCAN_NB, SCAN_B>>>();
    k_scanB<<<1, SCAN_B>>>();
    k_scanC<<<SCAN_NB, SCAN_B>>>();
    k_fill<<<(EE / 2 + 255) / 256, 256>>>(es, ed);

    // join
    cudaEventRecord(evJoin, s2);
    cudaStreamWaitEvent(0, evJoin, 0);

    k_agg1<<<(NN * 32 + 255) / 256, 256>>>(b1);
    k_gemm2<<<G_BLOCKS, G_THREADS, smem2>>>(as2w, ad2w);
    k_agg2<<<(NN * 32 + 255) / 256, 256>>>(b2, out);
}

// round 15
// speedup vs baseline: 1.0149x; 1.0088x over previous
#include <cuda_runtime.h>
#include <cuda_fp16.h>
#include <cstdint>
#include <math.h>

#define NN   50000
#define EE   850000
#define FIN  128
#define NH1  4
#define C1   50
#define HID  200
#define FOUT 40
#define K2P  208

#define SCAN_B 256
#define SCAN_NB ((NN + SCAN_B - 1) / SCAN_B)   // 196

// gemm tiling: 4 warps x 16 rows = 64 rows per block (R7 config)
#define G_THREADS 128
#define G_ROWS    64
#define XS_STRIDE  136
#define WT_STRIDE  136
#define XS2_STRIDE 216
#define WT2_STRIDE 216

#define NHALF 25024                       // split point, multiple of 64

// ---------------- scratch ----------------
__device__ __half g_H1h[NN * HID];
__device__ __half g_H2h[NN * K2P];
__device__ __half g_G2h[NN * FOUT];
__device__ __half g_W1t[HID * FIN];
__device__ __half g_W2t[FOUT * K2P];
__device__ float g_as1[NN * NH1];
__device__ float g_ad1[NN * NH1];
__device__ float g_as2[NN];
__device__ float g_ad2[NN];
__device__ int   g_deg[NN];
__device__ int   g_rowptr[NN + 1];
__device__ int   g_cursor[NN];
__device__ int   g_csrc[EE];
__device__ int   g_bsum[SCAN_NB];
__device__ int   g_boff[SCAN_NB];
__device__ int   g_flag32;

__device__ __forceinline__ int load_idx(const void* p, int e, int is64) {
    if (is64) return (int)((const long long*)p)[e];
    return ((const int*)p)[e];
}

// ---------------- prep: weights -> fp16 transposed (side stream) ----------
__global__ void k_prep(const float* __restrict__ W1, const float* __restrict__ W2) {
    int i = blockIdx.x * blockDim.x + threadIdx.x;
    if (i < FIN * HID) {
        int n = i / FIN, k = i % FIN;
        g_W1t[n * FIN + k] = __float2half_rn(W1[k * HID + n]);
    }
    if (i < FOUT * K2P) {
        int n = i / K2P, k = i % K2P;
        g_W2t[i] = (k < HID) ? __float2half_rn(W2[k * FOUT + n]) : __float2half_rn(0.f);
    }
}

// ---------------- graph build (R11 exact) ----------------
__global__ void k_reset(const void* src) {
    int i = blockIdx.x * blockDim.x + threadIdx.x;
    if (i == 0) g_flag32 = 0;
    if (i < NN) g_deg[i] = 0;
    if (i >= NN && i < NN + 4096) {
        int t = i - NN;
        if (((const int*)src)[2 * t + 1] != 0) atomicOr(&g_flag32, 1);
    }
}

__global__ void k_count(const void* dst) {
    int e = blockIdx.x * blockDim.x + threadIdx.x;
    if (e < EE) {
        int is64 = (g_flag32 == 0);
        int d = load_idx(dst, e, is64);
        atomicAdd(&g_deg[d], 1);
    }
}

__global__ void k_scanA() {
    __shared__ int sh[SCAN_B];
    int t = threadIdx.x;
    int i = blockIdx.x * SCAN_B + t;
    int v = (i < NN) ? g_deg[i] : 0;
    sh[t] = v;
    __syncthreads();
    #pragma unroll
    for (int off = 1; off < SCAN_B; off <<= 1) {
        int add = (t >= off) ? sh[t - off] : 0;
        __syncthreads();
        sh[t] += add;
        __syncthreads();
    }
    if (i < NN) g_rowptr[i] = sh[t] - v;
    if (t == SCAN_B - 1) g_bsum[blockIdx.x] = sh[t];
}

__global__ void k_scanB() {
    __shared__ int sh[SCAN_B];
    int t = threadIdx.x;
    int v = (t < SCAN_NB) ? g_bsum[t] : 0;
    sh[t] = v;
    __syncthreads();
    #pragma unroll
    for (int off = 1; off < SCAN_B; off <<= 1) {
        int add = (t >= off) ? sh[t - off] : 0;
        __syncthreads();
        sh[t] += add;
        __syncthreads();
    }
    if (t < SCAN_NB) g_boff[t] = sh[t] - v;
}

__global__ void k_scanC() {
    int i = blockIdx.x * SCAN_B + threadIdx.x;
    if (i < NN) {
        int r = g_rowptr[i] + g_boff[blockIdx.x];
        g_rowptr[i] = r;
        g_cursor[i] = r;
    }
    if (i == 0) g_rowptr[NN] = EE;
}

__global__ void k_fill(const void* src, const void* dst) {
    int e = blockIdx.x * blockDim.x + threadIdx.x;
    if (e < EE) {
        int is64 = (g_flag32 == 0);
        int s = load_idx(src, e, is64);
        int d = load_idx(dst, e, is64);
        int pos = atomicAdd(&g_cursor[d], 1);
        g_csrc[pos] = s;
    }
}

// ---------------- GEMM1 (tensor cores, 64 rows/block — R7) -----------------
__global__ void __launch_bounds__(G_THREADS) k_gemm1(
        const float* __restrict__ x,
        const float* __restrict__ aw_s, const float* __restrict__ aw_d) {
    extern __shared__ char smraw[];
    __half* xs = (__half*)smraw;                              // 64 x 136
    __half* wt = (__half*)(smraw + G_ROWS * XS_STRIDE * 2);   // 200 x 136
    float* As = (float*)(smraw + G_ROWS * XS_STRIDE * 2 + HID * WT_STRIDE * 2);
    float* Ad = As + HID;

    int tid = threadIdx.x;
    int rowbase = blockIdx.x * G_ROWS;

    for (int idx = tid; idx < G_ROWS * (FIN / 4); idx += G_THREADS) {
        int r = idx >> 5;
        int c4 = idx & 31;
        float4 v = (rowbase + r < NN) ? *(const float4*)(x + (size_t)(rowbase + r) * FIN + c4 * 4)
                                      : make_float4(0.f, 0.f, 0.f, 0.f);
        __half2 h01 = __float22half2_rn(make_float2(v.x, v.y));
        __half2 h23 = __float22half2_rn(make_float2(v.z, v.w));
        uint2 pk = make_uint2(*(unsigned int*)&h01, *(unsigned int*)&h23);
        *(uint2*)(xs + r * XS_STRIDE + c4 * 4) = pk;
    }
    for (int idx = tid; idx < HID * (FIN / 8); idx += G_THREADS) {
        int n = idx >> 4, c = idx & 15;
        *(uint4*)(wt + n * WT_STRIDE + c * 8) = *(const uint4*)(g_W1t + n * FIN + c * 8);
    }
    for (int i = tid; i < HID; i += G_THREADS) { As[i] = aw_s[i]; Ad[i] = aw_d[i]; }
    __syncthreads();

    int warp = tid >> 5, lane = tid & 31;
    int g = lane >> 2, t = lane & 3;
    int lrow0 = warp * 16 + g;

    float c[25][4];
    #pragma unroll
    for (int nt = 0; nt < 25; nt++) { c[nt][0] = c[nt][1] = c[nt][2] = c[nt][3] = 0.f; }

    #pragma unroll
    for (int ks = 0; ks < 8; ks++) {
        int k0 = ks * 16;
        unsigned int a0 = *(const unsigned int*)(xs + lrow0 * XS_STRIDE + k0 + 2 * t);
        unsigned int a1 = *(const unsigned int*)(xs + (lrow0 + 8) * XS_STRIDE + k0 + 2 * t);
        unsigned int a2 = *(const unsigned int*)(xs + lrow0 * XS_STRIDE + k0 + 2 * t + 8);
        unsigned int a3 = *(const unsigned int*)(xs + (lrow0 + 8) * XS_STRIDE + k0 + 2 * t + 8);
        #pragma unroll
        for (int nt = 0; nt < 25; nt++) {
            unsigned int b0 = *(const unsigned int*)(wt + (nt * 8 + g) * WT_STRIDE + k0 + 2 * t);
            unsigned int b1 = *(const unsigned int*)(wt + (nt * 8 + g) * WT_STRIDE + k0 + 2 * t + 8);
            asm volatile(
                "mma.sync.aligned.m16n8k16.row.col.f32.f16.f16.f32 "
                "{%0,%1,%2,%3},{%4,%5,%6,%7},{%8,%9},{%0,%1,%2,%3};"
                : "+f"(c[nt][0]), "+f"(c[nt][1]), "+f"(c[nt][2]), "+f"(c[nt][3])
                : "r"(a0), "r"(a1), "r"(a2), "r"(a3), "r"(b0), "r"(b1));
        }
    }

    int r0 = rowbase + lrow0;
    int r1 = r0 + 8;
    float psl0 = 0, psl1 = 0, psl2 = 0, psl3 = 0;
    float pdl0 = 0, pdl1 = 0, pdl2 = 0, pdl3 = 0;
    float psh0 = 0, psh1 = 0, psh2 = 0, psh3 = 0;
    float pdh0 = 0, pdh1 = 0, pdh2 = 0, pdh3 = 0;

    #pragma unroll
    for (int nt = 0; nt < 25; nt++) {
        int col = nt * 8 + 2 * t;
        int h = col / 50;
        float as0 = As[col], as1v = As[col + 1];
        float ad0 = Ad[col], ad1v = Ad[col + 1];
        float sl = c[nt][0] * as0 + c[nt][1] * as1v;
        float dl = c[nt][0] * ad0 + c[nt][1] * ad1v;
        float sh = c[nt][2] * as0 + c[nt][3] * as1v;
        float dh = c[nt][2] * ad0 + c[nt][3] * ad1v;
        if (h == 0)      { psl0 += sl; pdl0 += dl; psh0 += sh; pdh0 += dh; }
        else if (h == 1) { psl1 += sl; pdl1 += dl; psh1 += sh; pdh1 += dh; }
        else if (h == 2) { psl2 += sl; pdl2 += dl; psh2 += sh; pdh2 += dh; }
        else             { psl3 += sl; pdl3 += dl; psh3 += sh; pdh3 += dh; }
        if (r0 < NN) {
            __half2 p = __float22half2_rn(make_float2(c[nt][0], c[nt][1]));
            *(unsigned int*)(g_H1h + (size_t)r0 * HID + col) = *(unsigned int*)&p;
        }
        if (r1 < NN) {
            __half2 p = __float22half2_rn(make_float2(c[nt][2], c[nt][3]));
            *(unsigned int*)(g_H1h + (size_t)r1 * HID + col) = *(unsigned int*)&p;
        }
    }
    #pragma unroll
    for (int off = 1; off <= 2; off <<= 1) {
        psl0 += __shfl_xor_sync(~0u, psl0, off); psl1 += __shfl_xor_sync(~0u, psl1, off);
        psl2 += __shfl_xor_sync(~0u, psl2, off); psl3 += __shfl_xor_sync(~0u, psl3, off);
        pdl0 += __shfl_xor_sync(~0u, pdl0, off); pdl1 += __shfl_xor_sync(~0u, pdl1, off);
        pdl2 += __shfl_xor_sync(~0u, pdl2, off); pdl3 += __shfl_xor_sync(~0u, pdl3, off);
        psh0 += __shfl_xor_sync(~0u, psh0, off); psh1 += __shfl_xor_sync(~0u, psh1, off);
        psh2 += __shfl_xor_sync(~0u, psh2, off); psh3 += __shfl_xor_sync(~0u, psh3, off);
        pdh0 += __shfl_xor_sync(~0u, pdh0, off); pdh1 += __shfl_xor_sync(~0u, pdh1, off);
        pdh2 += __shfl_xor_sync(~0u, pdh2, off); pdh3 += __shfl_xor_sync(~0u, pdh3, off);
    }
    if (t == 0) {
        if (r0 < NN) {
            g_as1[r0 * 4 + 0] = psl0; g_as1[r0 * 4 + 1] = psl1;
            g_as1[r0 * 4 + 2] = psl2; g_as1[r0 * 4 + 3] = psl3;
            g_ad1[r0 * 4 + 0] = pdl0; g_ad1[r0 * 4 + 1] = pdl1;
            g_ad1[r0 * 4 + 2] = pdl2; g_ad1[r0 * 4 + 3] = pdl3;
        }
        if (r1 < NN) {
            g_as1[r1 * 4 + 0] = psh0; g_as1[r1 * 4 + 1] = psh1;
            g_as1[r1 * 4 + 2] = psh2; g_as1[r1 * 4 + 3] = psh3;
            g_ad1[r1 * 4 + 0] = pdh0; g_ad1[r1 * 4 + 1] = pdh1;
            g_ad1[r1 * 4 + 2] = pdh2; g_ad1[r1 * 4 + 3] = pdh3;
        }
    }
}

// ---------------- agg layer 1 (node-range variant of R11 champion) ---------
__global__ void k_agg1(const float* __restrict__ b1, int nodeBase, int nodeCnt) {
    int v = nodeBase + ((blockIdx.x * blockDim.x + threadIdx.x) >> 5);
    int lane = threadIdx.x & 31;
    if (v >= nodeBase + nodeCnt || v >= NN) return;
    int beg = g_rowptr[v], end = g_rowptr[v + 1];
    float4 adv = *(const float4*)(g_ad1 + v * 4);

    int hh[4];
    #pragma unroll
    for (int j = 0; j < 4; j++) hh[j] = (j * 32 + lane) / 25;
    float acc[4][2] = {{0,0},{0,0},{0,0},{0,0}};
    float s0 = 0.f, s1 = 0.f, s2 = 0.f, s3 = 0.f;

    for (int base = beg; base < end; base += 32) {
        int cnt = min(32, end - base);
        int u = 0; float p0 = 0.f, p1 = 0.f, p2 = 0.f, p3 = 0.f;
        if (lane < cnt) {
            u = __ldg(g_csrc + base + lane);
            float4 a = *(const float4*)(g_as1 + u * 4);
            float e0 = a.x + adv.x; e0 = e0 > 0.f ? e0 : 0.2f * e0;
            float e1 = a.y + adv.y; e1 = e1 > 0.f ? e1 : 0.2f * e1;
            float e2 = a.z + adv.z; e2 = e2 > 0.f ? e2 : 0.2f * e2;
            float e3 = a.w + adv.w; e3 = e3 > 0.f ? e3 : 0.2f * e3;
            p0 = __expf(e0); p1 = __expf(e1); p2 = __expf(e2); p3 = __expf(e3);
        }
        s0 += p0; s1 += p1; s2 += p2; s3 += p3;
        for (int t = 0; t < cnt; t++) {
            int uu = __shfl_sync(0xffffffffu, u, t);
            float q0 = __shfl_sync(0xffffffffu, p0, t);
            float q1 = __shfl_sync(0xffffffffu, p1, t);
            float q2 = __shfl_sync(0xffffffffu, p2, t);
            float q3 = __shfl_sync(0xffffffffu, p3, t);
            const __half2* hr = (const __half2*)(g_H1h + (size_t)uu * HID);
            #pragma unroll
            for (int j = 0; j < 4; j++) {
                if (j < 3 || lane < 4) {
                    float2 f = __half22float2(hr[j * 32 + lane]);
                    float q = hh[j] == 0 ? q0 : (hh[j] == 1 ? q1 : (hh[j] == 2 ? q2 : q3));
                    acc[j][0] = fmaf(q, f.x, acc[j][0]);
                    acc[j][1] = fmaf(q, f.y, acc[j][1]);
                }
            }
        }
    }
    #pragma unroll
    for (int off = 16; off; off >>= 1) {
        s0 += __shfl_xor_sync(~0u, s0, off); s1 += __shfl_xor_sync(~0u, s1, off);
        s2 += __shfl_xor_sync(~0u, s2, off); s3 += __shfl_xor_sync(~0u, s3, off);
    }
    float is0 = 1.f / s0, is1 = 1.f / s1, is2 = 1.f / s2, is3 = 1.f / s3;
    #pragma unroll
    for (int j = 0; j < 4; j++) {
        if (j < 3 || lane < 4) {
            int idx = j * 32 + lane;
            float iv = hh[j] == 0 ? is0 : (hh[j] == 1 ? is1 : (hh[j] == 2 ? is2 : is3));
            float v0 = acc[j][0] * iv + __ldg(b1 + 2 * idx);
            float v1 = acc[j][1] * iv + __ldg(b1 + 2 * idx + 1);
            v0 = v0 > 0.f ? v0 : expm1f(v0);
            v1 = v1 > 0.f ? v1 : expm1f(v1);
            __half2 p = __float22half2_rn(make_float2(v0, v1));
            *(unsigned int*)(g_H2h + (size_t)v * K2P + 2 * idx) = *(unsigned int*)&p;
        }
    }
}

// ---------------- GEMM2 (node-range variant of R7 champion) ----------------
__global__ void __launch_bounds__(G_THREADS) k_gemm2(
        const float* __restrict__ aw_s, const float* __restrict__ aw_d, int rowBase) {
    extern __shared__ char smraw[];
    __half* xs = (__half*)smraw;                               // 64 x 216
    __half* wt = (__half*)(smraw + G_ROWS * XS2_STRIDE * 2);   // 40 x 216
    float* As = (float*)(smraw + G_ROWS * XS2_STRIDE * 2 + FOUT * WT2_STRIDE * 2);
    float* Ad = As + FOUT;

    int tid = threadIdx.x;
    int rowbase = rowBase + blockIdx.x * G_ROWS;

    for (int idx = tid; idx < G_ROWS * 26; idx += G_THREADS) {
        int r = idx / 26, c = idx % 26;
        uint4 v;
        if (rowbase + r < NN) v = *(const uint4*)(g_H2h + (size_t)(rowbase + r) * K2P + c * 8);
        else v = make_uint4(0u, 0u, 0u, 0u);
        *(uint4*)(xs + r * XS2_STRIDE + c * 8) = v;
    }
    for (int idx = tid; idx < FOUT * 26; idx += G_THREADS) {
        int n = idx / 26, c = idx % 26;
        *(uint4*)(wt + n * WT2_STRIDE + c * 8) = *(const uint4*)(g_W2t + n * K2P + c * 8);
    }
    for (int i = tid; i < FOUT; i += G_THREADS) { As[i] = aw_s[i]; Ad[i] = aw_d[i]; }
    __syncthreads();

    int warp = tid >> 5, lane = tid & 31;
    int g = lane >> 2, t = lane & 3;
    int lrow0 = warp * 16 + g;

    float c[5][4];
    #pragma unroll
    for (int nt = 0; nt < 5; nt++) { c[nt][0] = c[nt][1] = c[nt][2] = c[nt][3] = 0.f; }

    #pragma unroll
    for (int ks = 0; ks < 13; ks++) {
        int k0 = ks * 16;
        unsigned int a0 = *(const unsigned int*)(xs + lrow0 * XS2_STRIDE + k0 + 2 * t);
        unsigned int a1 = *(const unsigned int*)(xs + (lrow0 + 8) * XS2_STRIDE + k0 + 2 * t);
        unsigned int a2 = *(const unsigned int*)(xs + lrow0 * XS2_STRIDE + k0 + 2 * t + 8);
        unsigned int a3 = *(const unsigned int*)(xs + (lrow0 + 8) * XS2_STRIDE + k0 + 2 * t + 8);
        #pragma unroll
        for (int nt = 0; nt < 5; nt++) {
            unsigned int b0 = *(const unsigned int*)(wt + (nt * 8 + g) * WT2_STRIDE + k0 + 2 * t);
            unsigned int b1 = *(const unsigned int*)(wt + (nt * 8 + g) * WT2_STRIDE + k0 + 2 * t + 8);
            asm volatile(
                "mma.sync.aligned.m16n8k16.row.col.f32.f16.f16.f32 "
                "{%0,%1,%2,%3},{%4,%5,%6,%7},{%8,%9},{%0,%1,%2,%3};"
                : "+f"(c[nt][0]), "+f"(c[nt][1]), "+f"(c[nt][2]), "+f"(c[nt][3])
                : "r"(a0), "r"(a1), "r"(a2), "r"(a3), "r"(b0), "r"(b1));
        }
    }

    int r0 = rowbase + lrow0;
    int r1 = r0 + 8;
    float psl = 0, pdl = 0, psh = 0, pdh = 0;
    #pragma unroll
    for (int nt = 0; nt < 5; nt++) {
        int col = nt * 8 + 2 * t;
        float as0 = As[col], as1v = As[col + 1];
        float ad0 = Ad[col], ad1v = Ad[col + 1];
        psl += c[nt][0] * as0 + c[nt][1] * as1v;
        pdl += c[nt][0] * ad0 + c[nt][1] * ad1v;
        psh += c[nt][2] * as0 + c[nt][3] * as1v;
        pdh += c[nt][2] * ad0 + c[nt][3] * ad1v;
        if (r0 < NN) {
            __half2 p = __float22half2_rn(make_float2(c[nt][0], c[nt][1]));
            *(unsigned int*)(g_G2h + (size_t)r0 * FOUT + col) = *(unsigned int*)&p;
        }
        if (r1 < NN) {
            __half2 p = __float22half2_rn(make_float2(c[nt][2], c[nt][3]));
            *(unsigned int*)(g_G2h + (size_t)r1 * FOUT + col) = *(unsigned int*)&p;
        }
    }
    #pragma unroll
    for (int off = 1; off <= 2; off <<= 1) {
        psl += __shfl_xor_sync(~0u, psl, off);
        pdl += __shfl_xor_sync(~0u, pdl, off);
        psh += __shfl_xor_sync(~0u, psh, off);
        pdh += __shfl_xor_sync(~0u, pdh, off);
    }
    if (t == 0) {
        if (r0 < NN) { g_as2[r0] = psl; g_ad2[r0] = pdl; }
        if (r1 < NN) { g_as2[r1] = psh; g_ad2[r1] = pdh; }
    }
}

// ---------------- agg layer 2 + log_softmax (R11 champion) -----------------
__global__ void k_agg2(const float* __restrict__ b2, float* __restrict__ out) {
    int v = (blockIdx.x * blockDim.x + threadIdx.x) >> 5;
    int lane = threadIdx.x & 31;
    if (v >= NN) return;
    int beg = g_rowptr[v], end = g_rowptr[v + 1];
    float adv = g_ad2[v];

    float s = 0.f;
    float cx = 0.f, cy = 0.f;
    for (int base = beg; base < end; base += 32) {
        int cnt = min(32, end - base);
        int u = 0; float p = 0.f;
        if (lane < cnt) {
            u = __ldg(g_csrc + base + lane);
            float e = __ldg(g_as2 + u) + adv; e = e > 0.f ? e : 0.2f * e;
            p = __expf(e);
        }
        s += p;
        for (int t = 0; t < cnt; t++) {
            int uu = __shfl_sync(0xffffffffu, u, t);
            float q = __shfl_sync(0xffffffffu, p, t);
            if (lane < 20) {
                float2 f = __half22float2(((const __half2*)(g_G2h + (size_t)uu * FOUT))[lane]);
                cx = fmaf(q, f.x, cx);
                cy = fmaf(q, f.y, cy);
            }
        }
    }
    #pragma unroll
    for (int off = 16; off; off >>= 1) s += __shfl_xor_sync(~0u, s, off);

    float inv = 1.f / s;
    float o0 = (lane < 20) ? cx * inv + __ldg(b2 + 2 * lane)     : -1e30f;
    float o1 = (lane < 20) ? cy * inv + __ldg(b2 + 2 * lane + 1) : -1e30f;

    float mx = fmaxf(o0, o1);
    #pragma unroll
    for (int off = 16; off; off >>= 1) mx = fmaxf(mx, __shfl_xor_sync(~0u, mx, off));
    float se = (lane < 20) ? (__expf(o0 - mx) + __expf(o1 - mx)) : 0.f;
    #pragma unroll
    for (int off = 16; off; off >>= 1) se += __shfl_xor_sync(~0u, se, off);
    float ls = logf(se);

    if (lane < 20) {
        out[v * FOUT + 2 * lane]     = o0 - mx - ls;
        out[v * FOUT + 2 * lane + 1] = o1 - mx - ls;
    }
}

// ---------------- launch: fork-join + agg1/gemm2 pipeline ----------------
extern "C" void kernel_launch(void* const* d_in, const int* in_sizes, int n_in,
                              void* d_out, int out_size) {
    const float* x    = (const float*)d_in[0];
    const void*  es   = d_in[1];
    const void*  ed   = d_in[2];
    const float* W1   = (const float*)d_in[3];
    const float* as1w = (const float*)d_in[4];
    const float* ad1w = (const float*)d_in[5];
    const float* b1   = (const float*)d_in[6];
    const float* W2   = (const float*)d_in[7];
    const float* as2w = (const float*)d_in[8];
    const float* ad2w = (const float*)d_in[9];
    const float* b2   = (const float*)d_in[10];
    float* out = (float*)d_out;

    static cudaStream_t s2 = 0;
    static cudaEvent_t evFork = 0, evJoin = 0, evA = 0, evB = 0;
    static int smemSet = 0;
    int smem1 = G_ROWS * XS_STRIDE * 2 + HID * WT_STRIDE * 2 + 2 * HID * 4;      // 73408
    int smem2 = G_ROWS * XS2_STRIDE * 2 + FOUT * WT2_STRIDE * 2 + 2 * FOUT * 4;  // 45248
    if (!s2) {
        cudaStreamCreateWithFlags(&s2, cudaStreamNonBlocking);
        cudaEventCreateWithFlags(&evFork, cudaEventDisableTiming);
        cudaEventCreateWithFlags(&evJoin, cudaEventDisableTiming);
        cudaEventCreateWithFlags(&evA, cudaEventDisableTiming);
        cudaEventCreateWithFlags(&evB, cudaEventDisableTiming);
    }
    if (!smemSet) {
        cudaFuncSetAttribute(k_gemm1, cudaFuncAttributeMaxDynamicSharedMemorySize, smem1);
        cudaFuncSetAttribute(k_gemm2, cudaFuncAttributeMaxDynamicSharedMemorySize, smem2);
        smemSet = 1;
    }

    // fork: side stream runs prep + gemm1 while default stream builds the CSR
    cudaEventRecord(evFork, 0);
    cudaStreamWaitEvent(s2, evFork, 0);

    k_prep<<<(FIN * HID + 255) / 256, 256, 0, s2>>>(W1, W2);
    k_gemm1<<<(NN + G_ROWS - 1) / G_ROWS, G_THREADS, smem1, s2>>>(x, as1w, ad1w);

    k_reset<<<(NN + 4096 + 255) / 256, 256>>>(es);
    k_count<<<(EE + 255) / 256, 256>>>(ed);
    k_scanA<<<SCAN_NB, SCAN_B>>>();
    k_scanB<<<1, SCAN_B>>>();
    k_scanC<<<SCAN_NB, SCAN_B>>>();
    k_fill<<<(EE + 255) / 256, 256>>>(es, ed);

    // join build + gemm1
    cudaEventRecord(evJoin, s2);
    cudaStreamWaitEvent(0, evJoin, 0);

    // pipeline: agg1(A) -> [gemm2(A) on s2 || agg1(B)] -> gemm2(B) -> agg2
    k_agg1<<<(NHALF * 32 + 255) / 256, 256>>>(b1, 0, NHALF);
    cudaEventRecord(evA, 0);
    k_agg1<<<((NN - NHALF) * 32 + 255) / 256, 256>>>(b1, NHALF, NN - NHALF);

    cudaStreamWaitEvent(s2, evA, 0);
    k_gemm2<<<NHALF / G_ROWS, G_THREADS, smem2, s2>>>(as2w, ad2w, 0);
    cudaEventRecord(evB, s2);

    k_gemm2<<<(NN - NHALF + G_ROWS - 1) / G_ROWS, G_THREADS, smem2>>>(as2w, ad2w, NHALF);
    cudaStreamWaitEvent(0, evB, 0);

    k_agg2<<<(NN * 32 + 255) / 256, 256>>>(b2, out);
}